// round 1
// baseline (speedup 1.0000x reference)
#include <cuda_runtime.h>

#define B_TOTAL 4096
#define DIM 64
#define KNB 16
#define NREL 33

__global__ __launch_bounds__(256, 1) void kgnn_kernel(
    const int* __restrict__ u_ids,
    const int* __restrict__ i_ids,
    const int* __restrict__ adj_entity,
    const int* __restrict__ adj_relation,
    const float* __restrict__ user_emb,
    const float* __restrict__ entity_emb,
    const float* __restrict__ relation_emb,
    const float* __restrict__ W0,
    const float* __restrict__ b0,
    const float* __restrict__ W1,
    const float* __restrict__ b1,
    float* __restrict__ out)
{
    __shared__ float rel_s[NREL * 65];     // padded rows: bank (r+d)%32
    __shared__ float W0_s[64 * 65];        // padded rows: conflict-free matvec
    __shared__ float ue_s[64];
    __shared__ float attn_s[16][16];
    __shared__ float attn0_s[16];
    __shared__ int   e1_s[16], r0_s[16];
    __shared__ int   e2_s[16][16];
    __shared__ float x_s[16][64];
    __shared__ float x0_s[64];
    __shared__ float h1_s[16][64];
    __shared__ float h0_s[64];
    __shared__ float red_s[2];

    const int b    = blockIdx.x;
    const int t    = threadIdx.x;
    const int lane = t & 31;
    const int w    = t >> 5;

    // ---- Phase 1: stage small tables + indices ----
    for (int idx = t; idx < NREL * 64; idx += 256) {
        int r = idx >> 6, d = idx & 63;
        rel_s[r * 65 + d] = relation_emb[idx];
    }
    for (int idx = t; idx < 64 * 64; idx += 256) {
        int e = idx >> 6, d = idx & 63;
        W0_s[e * 65 + d] = W0[idx];
    }
    if (t < 64) ue_s[t] = user_emb[u_ids[b] * 64 + t];
    const int e0 = i_ids[b];
    if (t < 16) {
        e1_s[t] = adj_entity[e0 * KNB + t];
        r0_s[t] = adj_relation[e0 * KNB + t];
    }
    __syncthreads();

    // ---- Phase 2: hop-1 indices + attention (thread per (j,k)) ----
    {
        const int j = t >> 4, k = t & 15;
        const int ej = e1_s[j];
        e2_s[j][k] = adj_entity[ej * KNB + k];
        const int r1 = adj_relation[ej * KNB + k];

        float s = 0.f;
        #pragma unroll
        for (int d = 0; d < 64; d++) s += ue_s[d] * rel_s[r1 * 65 + d];
        s *= (1.f / 64.f);                       // mean over DIM

        // softmax over the 16 k-lanes (lane-aligned groups)
        float m = s;
        #pragma unroll
        for (int o = 8; o; o >>= 1) m = fmaxf(m, __shfl_xor_sync(0xffffffffu, m, o));
        float ex = __expf(s - m);
        float sum = ex;
        #pragma unroll
        for (int o = 8; o; o >>= 1) sum += __shfl_xor_sync(0xffffffffu, sum, o);
        attn_s[j][k] = ex / sum * (1.f / 16.f);  // fold mean-over-K
    }
    // hop-0 attention (shared by layer0-hop0 and layer1-hop0): warp0 lanes 0-15
    if (t < 16) {
        const int r = r0_s[t];
        float s = 0.f;
        #pragma unroll
        for (int d = 0; d < 64; d++) s += ue_s[d] * rel_s[r * 65 + d];
        s *= (1.f / 64.f);
        float m = s;
        #pragma unroll
        for (int o = 8; o; o >>= 1) m = fmaxf(m, __shfl_xor_sync(0x0000ffffu, m, o));
        float ex = __expf(s - m);
        float sum = ex;
        #pragma unroll
        for (int o = 8; o; o >>= 1) sum += __shfl_xor_sync(0x0000ffffu, sum, o);
        attn0_s[t] = ex / sum * (1.f / 16.f);
    }
    __syncthreads();

    // ---- Phase 3: attention-weighted entity gathers (coalesced float2 rows) ----
    #pragma unroll
    for (int jj = 0; jj < 2; jj++) {
        const int j = w + jj * 8;
        float a0 = 0.f, a1 = 0.f;
        #pragma unroll
        for (int k = 0; k < 16; k++) {           // 16 independent LDG chains -> MLP
            const float2 v = ((const float2*)(entity_emb + e2_s[j][k] * 64))[lane];
            const float a = attn_s[j][k];
            a0 += a * v.x; a1 += a * v.y;
        }
        const float2 sv = ((const float2*)(entity_emb + e1_s[j] * 64))[lane];
        x_s[j][2 * lane]     = sv.x + a0;
        x_s[j][2 * lane + 1] = sv.y + a1;
    }
    if (w == 0) {   // hop-0 aggregate
        float a0 = 0.f, a1 = 0.f;
        #pragma unroll
        for (int k = 0; k < 16; k++) {
            const float2 v = ((const float2*)(entity_emb + e1_s[k] * 64))[lane];
            const float a = attn0_s[k];
            a0 += a * v.x; a1 += a * v.y;
        }
        const float2 sv = ((const float2*)(entity_emb + e0 * 64))[lane];
        x0_s[2 * lane]     = sv.x + a0;
        x0_s[2 * lane + 1] = sv.y + a1;
    }
    __syncthreads();

    // ---- Phase 4: layer-0 matvecs, out[e] = relu(b0[e] + x . W0[e,:]) ----
    {
        const int j  = t >> 4;     // 0..15
        const int eb = t & 15;     // 4 outputs: eb, eb+16, eb+32, eb+48
        float acc0 = b0[eb], acc1 = b0[eb + 16], acc2 = b0[eb + 32], acc3 = b0[eb + 48];
        #pragma unroll
        for (int d = 0; d < 64; d++) {
            const float xv = x_s[j][d];          // broadcast within j-group
            acc0 += xv * W0_s[(eb     ) * 65 + d];
            acc1 += xv * W0_s[(eb + 16) * 65 + d];
            acc2 += xv * W0_s[(eb + 32) * 65 + d];
            acc3 += xv * W0_s[(eb + 48) * 65 + d];
        }
        h1_s[j][eb]      = fmaxf(acc0, 0.f);
        h1_s[j][eb + 16] = fmaxf(acc1, 0.f);
        h1_s[j][eb + 32] = fmaxf(acc2, 0.f);
        h1_s[j][eb + 48] = fmaxf(acc3, 0.f);
    }
    if (t < 64) {
        float acc = b0[t];
        #pragma unroll
        for (int d = 0; d < 64; d++) acc += x0_s[d] * W0_s[t * 65 + d];
        h0_s[t] = fmaxf(acc, 0.f);
    }
    __syncthreads();

    // ---- Phase 5: layer-1 hop-0 (reuses attn0), tanh matvec, score ----
    if (t < 64) {
        float agg = 0.f;
        #pragma unroll
        for (int k = 0; k < 16; k++) agg += attn0_s[k] * h1_s[k][t];
        x0_s[t] = h0_s[t] + agg;   // reuse x0_s as final x (sync below)
    }
    __syncthreads();
    if (t < 64) {
        float acc = b1[t];
        #pragma unroll
        for (int d = 0; d < 64; d++) acc += x0_s[d] * W1[t * 64 + d];
        const float item = tanhf(acc);
        float p = ue_s[t] * item;
        #pragma unroll
        for (int o = 16; o; o >>= 1) p += __shfl_xor_sync(0xffffffffu, p, o);
        if (lane == 0) red_s[w] = p;
    }
    __syncthreads();
    if (t == 0) {
        const float s = red_s[0] + red_s[1];
        out[b] = 1.f / (1.f + __expf(-s));
    }
}

extern "C" void kernel_launch(void* const* d_in, const int* in_sizes, int n_in,
                              void* d_out, int out_size) {
    const int*   u_ids        = (const int*)d_in[0];
    const int*   i_ids        = (const int*)d_in[1];
    const int*   adj_entity   = (const int*)d_in[2];
    const int*   adj_relation = (const int*)d_in[3];
    const float* user_emb     = (const float*)d_in[4];
    const float* entity_emb   = (const float*)d_in[5];
    const float* relation_emb = (const float*)d_in[6];
    const float* W0           = (const float*)d_in[7];
    const float* b0           = (const float*)d_in[8];
    const float* W1           = (const float*)d_in[9];
    const float* b1           = (const float*)d_in[10];
    float* out = (float*)d_out;

    const int B = in_sizes[1];   // i_ids count = batch
    kgnn_kernel<<<B, 256>>>(u_ids, i_ids, adj_entity, adj_relation,
                            user_emb, entity_emb, relation_emb,
                            W0, b0, W1, b1, out);
}

// round 3
// speedup vs baseline: 1.9947x; 1.9947x over previous
#include <cuda_runtime.h>

#define DIM 64
#define KNB 16
#define NREL 33
#define W0PAD 17   // float4 per row (68 floats) -> conflict-free LDS.128

__global__ __launch_bounds__(256, 4) void kgnn_kernel(
    const int* __restrict__ u_ids,
    const int* __restrict__ i_ids,
    const int* __restrict__ adj_entity,
    const int* __restrict__ adj_relation,
    const float* __restrict__ user_emb,
    const float* __restrict__ entity_emb,
    const float* __restrict__ relation_emb,
    const float* __restrict__ W0,
    const float* __restrict__ b0,
    const float* __restrict__ W1,
    const float* __restrict__ b1,
    float* __restrict__ out)
{
    __shared__ float4 W0_s[64 * W0PAD];
    __shared__ float  ue_s[64];
    __shared__ float  reldot_s[NREL];
    __shared__ float  attn_s[16][16];
    __shared__ float  attn0_s[16];
    __shared__ int    e1_s[16], r0_s[16];
    __shared__ int    e2_s[16][16];
    __shared__ int    r1_s[16][16];
    __shared__ __align__(16) float x_s[16][64];
    __shared__ __align__(16) float x0_s[64];
    __shared__ float  h1_s[16][64];
    __shared__ float  h0_s[64];
    __shared__ float  red_s[2];

    const int b    = blockIdx.x;
    const int t    = threadIdx.x;
    const int lane = t & 31;
    const int w    = t >> 5;

    // ---- P1: stage ue, W0 (vectorized), hop-0 indices ----
    {
        const float4* W0_4 = (const float4*)W0;
        #pragma unroll
        for (int i = 0; i < 4; i++) {
            int idx = t + i * 256;              // 1024 float4 total
            int e = idx >> 4, c = idx & 15;
            W0_s[e * W0PAD + c] = W0_4[idx];
        }
    }
    if (t < 64) ue_s[t] = user_emb[u_ids[b] * 64 + t];
    const int e0 = i_ids[b];
    if (t < 16) {
        e1_s[t] = adj_entity[e0 * KNB + t];
        r0_s[t] = adj_relation[e0 * KNB + t];
    }
    __syncthreads();

    // ---- P2: 33 relation dots (warp-parallel) + hop-1 index loads ----
    for (int r = w; r < NREL; r += 8) {
        float p = ue_s[lane] * relation_emb[r * 64 + lane]
                + ue_s[lane + 32] * relation_emb[r * 64 + 32 + lane];
        #pragma unroll
        for (int o = 16; o; o >>= 1) p += __shfl_xor_sync(0xffffffffu, p, o);
        if (lane == 0) reldot_s[r] = p * (1.f / 64.f);
    }
    {
        const int j = t >> 4, k = t & 15;
        const int ej = e1_s[j];
        e2_s[j][k] = adj_entity[ej * KNB + k];
        r1_s[j][k] = adj_relation[ej * KNB + k];
    }
    __syncthreads();

    // ---- P3: attention via lookup + 16-lane softmax ----
    {
        const int j = t >> 4, k = t & 15;
        float s = reldot_s[r1_s[j][k]];
        float m = s;
        #pragma unroll
        for (int o = 8; o; o >>= 1) m = fmaxf(m, __shfl_xor_sync(0xffffffffu, m, o));
        float ex = __expf(s - m);
        float sum = ex;
        #pragma unroll
        for (int o = 8; o; o >>= 1) sum += __shfl_xor_sync(0xffffffffu, sum, o);
        attn_s[j][k] = ex / sum * (1.f / 16.f);
    }
    if (t < 16) {
        float s = reldot_s[r0_s[t]];
        float m = s;
        #pragma unroll
        for (int o = 8; o; o >>= 1) m = fmaxf(m, __shfl_xor_sync(0x0000ffffu, m, o));
        float ex = __expf(s - m);
        float sum = ex;
        #pragma unroll
        for (int o = 8; o; o >>= 1) sum += __shfl_xor_sync(0x0000ffffu, sum, o);
        attn0_s[t] = ex / sum * (1.f / 16.f);
    }
    __syncthreads();

    // ---- P4: float4 entity gathers (half-warp per row, even/odd k split) ----
    const int half = lane >> 4;
    const int c    = lane & 15;
    #pragma unroll
    for (int jj = 0; jj < 2; jj++) {
        const int j = w + jj * 8;
        float4 acc = make_float4(0.f, 0.f, 0.f, 0.f);
        #pragma unroll
        for (int kk = 0; kk < 8; kk++) {
            const int k = kk * 2 + half;
            const float4 v = ((const float4*)(entity_emb + e2_s[j][k] * 64))[c];
            const float a = attn_s[j][k];
            acc.x += a * v.x; acc.y += a * v.y; acc.z += a * v.z; acc.w += a * v.w;
        }
        acc.x += __shfl_xor_sync(0xffffffffu, acc.x, 16);
        acc.y += __shfl_xor_sync(0xffffffffu, acc.y, 16);
        acc.z += __shfl_xor_sync(0xffffffffu, acc.z, 16);
        acc.w += __shfl_xor_sync(0xffffffffu, acc.w, 16);
        if (half == 0) {
            const float4 sv = ((const float4*)(entity_emb + e1_s[j] * 64))[c];
            ((float4*)x_s[j])[c] = make_float4(sv.x + acc.x, sv.y + acc.y,
                                               sv.z + acc.z, sv.w + acc.w);
        }
    }
    if (w == 0) {  // hop-0 aggregate
        float4 acc = make_float4(0.f, 0.f, 0.f, 0.f);
        #pragma unroll
        for (int kk = 0; kk < 8; kk++) {
            const int k = kk * 2 + half;
            const float4 v = ((const float4*)(entity_emb + e1_s[k] * 64))[c];
            const float a = attn0_s[k];
            acc.x += a * v.x; acc.y += a * v.y; acc.z += a * v.z; acc.w += a * v.w;
        }
        acc.x += __shfl_xor_sync(0xffffffffu, acc.x, 16);
        acc.y += __shfl_xor_sync(0xffffffffu, acc.y, 16);
        acc.z += __shfl_xor_sync(0xffffffffu, acc.z, 16);
        acc.w += __shfl_xor_sync(0xffffffffu, acc.w, 16);
        if (half == 0) {
            const float4 sv = ((const float4*)(entity_emb + e0 * 64))[c];
            ((float4*)x0_s)[c] = make_float4(sv.x + acc.x, sv.y + acc.y,
                                             sv.z + acc.z, sv.w + acc.w);
        }
    }
    __syncthreads();

    // ---- P5: layer-0 matvecs (LDS.128, conflict-free), relu ----
    {
        const int j  = t >> 4;
        const int eb = t & 15;
        float acc0 = b0[eb], acc1 = b0[eb + 16], acc2 = b0[eb + 32], acc3 = b0[eb + 48];
        const float4* xj = (const float4*)x_s[j];
        #pragma unroll
        for (int dd = 0; dd < 16; dd++) {
            const float4 xv = xj[dd];
            const float4 w0 = W0_s[(eb     ) * W0PAD + dd];
            const float4 w1v = W0_s[(eb + 16) * W0PAD + dd];
            const float4 w2 = W0_s[(eb + 32) * W0PAD + dd];
            const float4 w3 = W0_s[(eb + 48) * W0PAD + dd];
            acc0 += xv.x * w0.x + xv.y * w0.y + xv.z * w0.z + xv.w * w0.w;
            acc1 += xv.x * w1v.x + xv.y * w1v.y + xv.z * w1v.z + xv.w * w1v.w;
            acc2 += xv.x * w2.x + xv.y * w2.y + xv.z * w2.z + xv.w * w2.w;
            acc3 += xv.x * w3.x + xv.y * w3.y + xv.z * w3.z + xv.w * w3.w;
        }
        h1_s[j][eb]      = fmaxf(acc0, 0.f);
        h1_s[j][eb + 16] = fmaxf(acc1, 0.f);
        h1_s[j][eb + 32] = fmaxf(acc2, 0.f);
        h1_s[j][eb + 48] = fmaxf(acc3, 0.f);
    }
    if (t < 64) {
        float acc = b0[t];
        const float4* x0v = (const float4*)x0_s;
        #pragma unroll
        for (int dd = 0; dd < 16; dd++) {
            const float4 xv = x0v[dd];
            const float4 wv = W0_s[t * W0PAD + dd];
            acc += xv.x * wv.x + xv.y * wv.y + xv.z * wv.z + xv.w * wv.w;
        }
        h0_s[t] = fmaxf(acc, 0.f);
    }
    __syncthreads();

    // ---- P6: layer-1 hop-0 (reuses attn0), tanh matvec, score ----
    if (t < 64) {
        float agg = 0.f;
        #pragma unroll
        for (int k = 0; k < 16; k++) agg += attn0_s[k] * h1_s[k][t];
        x0_s[t] = h0_s[t] + agg;
    }
    __syncthreads();
    if (t < 64) {
        float acc = b1[t];
        const float4* w1r = (const float4*)(W1 + t * 64);
        const float4* x0v = (const float4*)x0_s;
        #pragma unroll
        for (int dd = 0; dd < 16; dd++) {
            const float4 xv = x0v[dd];
            const float4 wv = w1r[dd];
            acc += xv.x * wv.x + xv.y * wv.y + xv.z * wv.z + xv.w * wv.w;
        }
        const float item = tanhf(acc);
        float p = ue_s[t] * item;
        #pragma unroll
        for (int o = 16; o; o >>= 1) p += __shfl_xor_sync(0xffffffffu, p, o);
        if (lane == 0) red_s[w] = p;
    }
    __syncthreads();
    if (t == 0) {
        const float s = red_s[0] + red_s[1];
        out[b] = 1.f / (1.f + __expf(-s));
    }
}

extern "C" void kernel_launch(void* const* d_in, const int* in_sizes, int n_in,
                              void* d_out, int out_size) {
    const int*   u_ids        = (const int*)d_in[0];
    const int*   i_ids        = (const int*)d_in[1];
    const int*   adj_entity   = (const int*)d_in[2];
    const int*   adj_relation = (const int*)d_in[3];
    const float* user_emb     = (const float*)d_in[4];
    const float* entity_emb   = (const float*)d_in[5];
    const float* relation_emb = (const float*)d_in[6];
    const float* W0           = (const float*)d_in[7];
    const float* b0           = (const float*)d_in[8];
    const float* W1           = (const float*)d_in[9];
    const float* b1           = (const float*)d_in[10];
    float* out = (float*)d_out;

    const int B = in_sizes[1];
    kgnn_kernel<<<B, 256>>>(u_ids, i_ids, adj_entity, adj_relation,
                            user_emb, entity_emb, relation_emb,
                            W0, b0, W1, b1, out);
}

// round 4
// speedup vs baseline: 2.4351x; 1.2208x over previous
#include <cuda_runtime.h>

#define DIM 64
#define KNB 16
#define NREL 33
#define W0PAD 17   // float4 per row (68 floats) -> conflict-free LDS.128

__global__ __launch_bounds__(256, 4) void kgnn_kernel(
    const int* __restrict__ u_ids,
    const int* __restrict__ i_ids,
    const int* __restrict__ adj_entity,
    const int* __restrict__ adj_relation,
    const float* __restrict__ user_emb,
    const float* __restrict__ entity_emb,
    const float* __restrict__ relation_emb,
    const float* __restrict__ W0,
    const float* __restrict__ b0,
    const float* __restrict__ W1,
    const float* __restrict__ b1,
    float* __restrict__ out)
{
    __shared__ float4 W0_s[64 * W0PAD];
    __shared__ float  ue_s[64];
    __shared__ float  reldot_s[NREL];
    __shared__ float  attn_s[16][16];
    __shared__ float  attn0_s[16];
    __shared__ int    e1_s[16], r0_s[16];
    __shared__ int    e2_s[16][16];
    __shared__ int    r1_s[16][16];
    __shared__ __align__(16) float x_s[16][64];
    __shared__ __align__(16) float x0_s[64];
    __shared__ float  h1_s[16][64];
    __shared__ float  h0_s[64];
    __shared__ float  red_s[2];

    const int b    = blockIdx.x;
    const int t    = threadIdx.x;
    const int lane = t & 31;
    const int w    = t >> 5;

    // ---- P1: stage ue, W0 (vectorized), hop-0 indices ----
    {
        const float4* W0_4 = (const float4*)W0;
        #pragma unroll
        for (int i = 0; i < 4; i++) {
            int idx = t + i * 256;              // 1024 float4 total
            int e = idx >> 4, c = idx & 15;
            W0_s[e * W0PAD + c] = W0_4[idx];
        }
    }
    if (t < 64) ue_s[t] = user_emb[u_ids[b] * 64 + t];
    const int e0 = i_ids[b];
    if (t < 16) {
        e1_s[t] = adj_entity[e0 * KNB + t];
        r0_s[t] = adj_relation[e0 * KNB + t];
    }
    __syncthreads();

    // ---- P2: 33 relation dots (warp-parallel) + hop-1 index loads ----
    for (int r = w; r < NREL; r += 8) {
        float p = ue_s[lane] * relation_emb[r * 64 + lane]
                + ue_s[lane + 32] * relation_emb[r * 64 + 32 + lane];
        #pragma unroll
        for (int o = 16; o; o >>= 1) p += __shfl_xor_sync(0xffffffffu, p, o);
        if (lane == 0) reldot_s[r] = p * (1.f / 64.f);
    }
    {
        const int j = t >> 4, k = t & 15;
        const int ej = e1_s[j];
        e2_s[j][k] = adj_entity[ej * KNB + k];
        r1_s[j][k] = adj_relation[ej * KNB + k];
    }
    __syncthreads();

    // ---- P3: attention via lookup + 16-lane softmax ----
    {
        const int j = t >> 4, k = t & 15;
        float s = reldot_s[r1_s[j][k]];
        float m = s;
        #pragma unroll
        for (int o = 8; o; o >>= 1) m = fmaxf(m, __shfl_xor_sync(0xffffffffu, m, o));
        float ex = __expf(s - m);
        float sum = ex;
        #pragma unroll
        for (int o = 8; o; o >>= 1) sum += __shfl_xor_sync(0xffffffffu, sum, o);
        attn_s[j][k] = ex / sum * (1.f / 16.f);
    }
    if (t < 16) {
        float s = reldot_s[r0_s[t]];
        float m = s;
        #pragma unroll
        for (int o = 8; o; o >>= 1) m = fmaxf(m, __shfl_xor_sync(0x0000ffffu, m, o));
        float ex = __expf(s - m);
        float sum = ex;
        #pragma unroll
        for (int o = 8; o; o >>= 1) sum += __shfl_xor_sync(0x0000ffffu, sum, o);
        attn0_s[t] = ex / sum * (1.f / 16.f);
    }
    __syncthreads();

    // ---- P4: float4 entity gathers (half-warp per row, even/odd k split) ----
    const int half = lane >> 4;
    const int c    = lane & 15;
    #pragma unroll
    for (int jj = 0; jj < 2; jj++) {
        const int j = w + jj * 8;
        float4 acc = make_float4(0.f, 0.f, 0.f, 0.f);
        #pragma unroll
        for (int kk = 0; kk < 8; kk++) {
            const int k = kk * 2 + half;
            const float4 v = ((const float4*)(entity_emb + e2_s[j][k] * 64))[c];
            const float a = attn_s[j][k];
            acc.x += a * v.x; acc.y += a * v.y; acc.z += a * v.z; acc.w += a * v.w;
        }
        acc.x += __shfl_xor_sync(0xffffffffu, acc.x, 16);
        acc.y += __shfl_xor_sync(0xffffffffu, acc.y, 16);
        acc.z += __shfl_xor_sync(0xffffffffu, acc.z, 16);
        acc.w += __shfl_xor_sync(0xffffffffu, acc.w, 16);
        if (half == 0) {
            const float4 sv = ((const float4*)(entity_emb + e1_s[j] * 64))[c];
            ((float4*)x_s[j])[c] = make_float4(sv.x + acc.x, sv.y + acc.y,
                                               sv.z + acc.z, sv.w + acc.w);
        }
    }
    if (w == 0) {  // hop-0 aggregate
        float4 acc = make_float4(0.f, 0.f, 0.f, 0.f);
        #pragma unroll
        for (int kk = 0; kk < 8; kk++) {
            const int k = kk * 2 + half;
            const float4 v = ((const float4*)(entity_emb + e1_s[k] * 64))[c];
            const float a = attn0_s[k];
            acc.x += a * v.x; acc.y += a * v.y; acc.z += a * v.z; acc.w += a * v.w;
        }
        acc.x += __shfl_xor_sync(0xffffffffu, acc.x, 16);
        acc.y += __shfl_xor_sync(0xffffffffu, acc.y, 16);
        acc.z += __shfl_xor_sync(0xffffffffu, acc.z, 16);
        acc.w += __shfl_xor_sync(0xffffffffu, acc.w, 16);
        if (half == 0) {
            const float4 sv = ((const float4*)(entity_emb + e0 * 64))[c];
            ((float4*)x0_s)[c] = make_float4(sv.x + acc.x, sv.y + acc.y,
                                             sv.z + acc.z, sv.w + acc.w);
        }
    }
    __syncthreads();

    // ---- P5: layer-0 matvecs, relu ----
    if (w < 4) {
        // warp w handles j = 4w..4w+3; each thread: e in {lane, lane+32} x 4 j
        const int j0 = w * 4;
        const float bl = b0[lane], bh = b0[lane + 32];
        float a0l = bl, a0h = bh, a1l = bl, a1h = bh;
        float a2l = bl, a2h = bh, a3l = bl, a3h = bh;
        const float4* x0p = (const float4*)x_s[j0];
        const float4* x1p = (const float4*)x_s[j0 + 1];
        const float4* x2p = (const float4*)x_s[j0 + 2];
        const float4* x3p = (const float4*)x_s[j0 + 3];
        #pragma unroll
        for (int dd = 0; dd < 16; dd++) {
            const float4 wl = W0_s[lane * W0PAD + dd];          // 32 distinct rows
            const float4 wh = W0_s[(lane + 32) * W0PAD + dd];   // 32 distinct rows
            const float4 xv0 = x0p[dd];   // uniform broadcast
            const float4 xv1 = x1p[dd];
            const float4 xv2 = x2p[dd];
            const float4 xv3 = x3p[dd];
            a0l += xv0.x*wl.x + xv0.y*wl.y + xv0.z*wl.z + xv0.w*wl.w;
            a0h += xv0.x*wh.x + xv0.y*wh.y + xv0.z*wh.z + xv0.w*wh.w;
            a1l += xv1.x*wl.x + xv1.y*wl.y + xv1.z*wl.z + xv1.w*wl.w;
            a1h += xv1.x*wh.x + xv1.y*wh.y + xv1.z*wh.z + xv1.w*wh.w;
            a2l += xv2.x*wl.x + xv2.y*wl.y + xv2.z*wl.z + xv2.w*wl.w;
            a2h += xv2.x*wh.x + xv2.y*wh.y + xv2.z*wh.z + xv2.w*wh.w;
            a3l += xv3.x*wl.x + xv3.y*wl.y + xv3.z*wl.z + xv3.w*wl.w;
            a3h += xv3.x*wh.x + xv3.y*wh.y + xv3.z*wh.z + xv3.w*wh.w;
        }
        h1_s[j0    ][lane]      = fmaxf(a0l, 0.f);
        h1_s[j0    ][lane + 32] = fmaxf(a0h, 0.f);
        h1_s[j0 + 1][lane]      = fmaxf(a1l, 0.f);
        h1_s[j0 + 1][lane + 32] = fmaxf(a1h, 0.f);
        h1_s[j0 + 2][lane]      = fmaxf(a2l, 0.f);
        h1_s[j0 + 2][lane + 32] = fmaxf(a2h, 0.f);
        h1_s[j0 + 3][lane]      = fmaxf(a3l, 0.f);
        h1_s[j0 + 3][lane + 32] = fmaxf(a3h, 0.f);
    } else if (w < 6) {
        // hop-0 matvec on warps 4-5
        const int e = t - 128;   // 0..63
        float acc = b0[e];
        const float4* x0v = (const float4*)x0_s;
        #pragma unroll
        for (int dd = 0; dd < 16; dd++) {
            const float4 xv = x0v[dd];
            const float4 wv = W0_s[e * W0PAD + dd];
            acc += xv.x * wv.x + xv.y * wv.y + xv.z * wv.z + xv.w * wv.w;
        }
        h0_s[e] = fmaxf(acc, 0.f);
    }
    __syncthreads();

    // ---- P6: layer-1 hop-0 (reuses attn0), tanh matvec, score ----
    if (t < 64) {
        float agg = 0.f;
        #pragma unroll
        for (int k = 0; k < 16; k++) agg += attn0_s[k] * h1_s[k][t];
        x0_s[t] = h0_s[t] + agg;
    }
    __syncthreads();
    if (t < 64) {
        float acc = b1[t];
        const float4* w1r = (const float4*)(W1 + t * 64);
        const float4* x0v = (const float4*)x0_s;
        #pragma unroll
        for (int dd = 0; dd < 16; dd++) {
            const float4 xv = x0v[dd];
            const float4 wv = w1r[dd];
            acc += xv.x * wv.x + xv.y * wv.y + xv.z * wv.z + xv.w * wv.w;
        }
        const float item = tanhf(acc);
        float p = ue_s[t] * item;
        #pragma unroll
        for (int o = 16; o; o >>= 1) p += __shfl_xor_sync(0xffffffffu, p, o);
        if (lane == 0) red_s[w] = p;
    }
    __syncthreads();
    if (t == 0) {
        const float s = red_s[0] + red_s[1];
        out[b] = 1.f / (1.f + __expf(-s));
    }
}

extern "C" void kernel_launch(void* const* d_in, const int* in_sizes, int n_in,
                              void* d_out, int out_size) {
    const int*   u_ids        = (const int*)d_in[0];
    const int*   i_ids        = (const int*)d_in[1];
    const int*   adj_entity   = (const int*)d_in[2];
    const int*   adj_relation = (const int*)d_in[3];
    const float* user_emb     = (const float*)d_in[4];
    const float* entity_emb   = (const float*)d_in[5];
    const float* relation_emb = (const float*)d_in[6];
    const float* W0           = (const float*)d_in[7];
    const float* b0           = (const float*)d_in[8];
    const float* W1           = (const float*)d_in[9];
    const float* b1           = (const float*)d_in[10];
    float* out = (float*)d_out;

    const int B = in_sizes[1];
    kgnn_kernel<<<B, 256>>>(u_ids, i_ids, adj_entity, adj_relation,
                            user_emb, entity_emb, relation_emb,
                            W0, b0, W1, b1, out);
}

// round 5
// speedup vs baseline: 2.5042x; 1.0284x over previous
#include <cuda_runtime.h>

#define DIM 64
#define KNB 16
#define NREL 33
#define W0PAD 17   // float4 per row -> conflict-free LDS.128 (bank stride 4 per lane)

__global__ __launch_bounds__(256, 4) void kgnn_kernel(
    const int* __restrict__ u_ids,
    const int* __restrict__ i_ids,
    const int* __restrict__ adj_entity,
    const int* __restrict__ adj_relation,
    const float* __restrict__ user_emb,
    const float* __restrict__ entity_emb,
    const float* __restrict__ relation_emb,
    const float* __restrict__ W0,
    const float* __restrict__ b0,
    const float* __restrict__ W1,
    const float* __restrict__ b1,
    float* __restrict__ out,
    int B)
{
    __shared__ float4 W0_s[64 * W0PAD];
    __shared__ float  ue_s[2][64];
    __shared__ float  reldot_s[2][NREL];
    __shared__ float  attn_s[2][16][16];
    __shared__ float  attn0_s[2][16];
    __shared__ int    e1_s[2][16], r0_s[2][16];
    __shared__ int    e2_s[2][16][16];
    __shared__ int    r1_s[2][16][16];
    __shared__ __align__(16) float x_s[2][16][64];
    __shared__ __align__(16) float x0_s[2][64];
    __shared__ float  h1_s[2][16][64];
    __shared__ float  h0_s[2][64];
    __shared__ float  red_s[2][2];

    const int b    = blockIdx.x;
    const int t    = threadIdx.x;
    const int lane = t & 31;
    const int w    = t >> 5;
    const int bi0  = 2 * b;
    const int bi1  = (2 * b + 1 < B) ? (2 * b + 1) : (B - 1);

    // ---- P1: stage W0 (vectorized), ue x2, hop-0 indices x2 ----
    {
        const float4* W0_4 = (const float4*)W0;
        #pragma unroll
        for (int i = 0; i < 4; i++) {
            int idx = t + i * 256;
            int e = idx >> 4, c = idx & 15;
            W0_s[e * W0PAD + c] = W0_4[idx];
        }
    }
    if (t < 128) {
        const int elem = t >> 6, d = t & 63;
        const int bi = elem ? bi1 : bi0;
        ue_s[elem][d] = user_emb[u_ids[bi] * 64 + d];
    }
    if (t < 32) {
        const int elem = t >> 4, kk = t & 15;
        const int bi = elem ? bi1 : bi0;
        const int e0 = i_ids[bi];
        e1_s[elem][kk] = adj_entity[e0 * KNB + kk];
        r0_s[elem][kk] = adj_relation[e0 * KNB + kk];
    }
    __syncthreads();

    // ---- P2: 66 relation dots + hop-1 index loads x2 ----
    for (int idx = w; idx < 2 * NREL; idx += 8) {
        const int r = idx >> 1, elem = idx & 1;
        float p = ue_s[elem][lane] * relation_emb[r * 64 + lane]
                + ue_s[elem][lane + 32] * relation_emb[r * 64 + 32 + lane];
        #pragma unroll
        for (int o = 16; o; o >>= 1) p += __shfl_xor_sync(0xffffffffu, p, o);
        if (lane == 0) reldot_s[elem][r] = p * (1.f / 64.f);
    }
    {
        const int j = t >> 4, k = t & 15;
        #pragma unroll
        for (int elem = 0; elem < 2; elem++) {
            const int ej = e1_s[elem][j];
            e2_s[elem][j][k] = adj_entity[ej * KNB + k];
            r1_s[elem][j][k] = adj_relation[ej * KNB + k];
        }
    }
    __syncthreads();

    // ---- P3: attention lookup + 16-lane softmax (both elems) ----
    {
        const int j = t >> 4, k = t & 15;
        #pragma unroll
        for (int elem = 0; elem < 2; elem++) {
            float s = reldot_s[elem][r1_s[elem][j][k]];
            float m = s;
            #pragma unroll
            for (int o = 8; o; o >>= 1) m = fmaxf(m, __shfl_xor_sync(0xffffffffu, m, o));
            float ex = __expf(s - m);
            float sum = ex;
            #pragma unroll
            for (int o = 8; o; o >>= 1) sum += __shfl_xor_sync(0xffffffffu, sum, o);
            attn_s[elem][j][k] = ex / sum * (1.f / 16.f);
        }
    }
    if (t < 32) {
        const int elem = t >> 4, k = t & 15;
        float s = reldot_s[elem][r0_s[elem][k]];
        float m = s;
        #pragma unroll
        for (int o = 8; o; o >>= 1) m = fmaxf(m, __shfl_xor_sync(0xffffffffu, m, o));
        float ex = __expf(s - m);
        float sum = ex;
        #pragma unroll
        for (int o = 8; o; o >>= 1) sum += __shfl_xor_sync(0xffffffffu, sum, o);
        attn0_s[elem][k] = ex / sum * (1.f / 16.f);
    }
    __syncthreads();

    // ---- P4: float4 entity gathers: 32 j rows + 2 hop-0 aggregates ----
    const int half = lane >> 4;
    const int c    = lane & 15;
    #pragma unroll
    for (int jj = 0; jj < 4; jj++) {
        const int jg   = w + jj * 8;          // 0..31
        const int elem = jg >> 4, j = jg & 15;
        float4 acc = make_float4(0.f, 0.f, 0.f, 0.f);
        #pragma unroll
        for (int kk = 0; kk < 8; kk++) {
            const int k = kk * 2 + half;
            const float4 v = ((const float4*)(entity_emb + e2_s[elem][j][k] * 64))[c];
            const float a = attn_s[elem][j][k];
            acc.x += a * v.x; acc.y += a * v.y; acc.z += a * v.z; acc.w += a * v.w;
        }
        acc.x += __shfl_xor_sync(0xffffffffu, acc.x, 16);
        acc.y += __shfl_xor_sync(0xffffffffu, acc.y, 16);
        acc.z += __shfl_xor_sync(0xffffffffu, acc.z, 16);
        acc.w += __shfl_xor_sync(0xffffffffu, acc.w, 16);
        if (half == 0) {
            const float4 sv = ((const float4*)(entity_emb + e1_s[elem][j] * 64))[c];
            ((float4*)x_s[elem][j])[c] = make_float4(sv.x + acc.x, sv.y + acc.y,
                                                     sv.z + acc.z, sv.w + acc.w);
        }
    }
    if (w < 2) {  // hop-0 aggregate, warp w -> elem w
        const int elem = w;
        const int bi = elem ? bi1 : bi0;
        float4 acc = make_float4(0.f, 0.f, 0.f, 0.f);
        #pragma unroll
        for (int kk = 0; kk < 8; kk++) {
            const int k = kk * 2 + half;
            const float4 v = ((const float4*)(entity_emb + e1_s[elem][k] * 64))[c];
            const float a = attn0_s[elem][k];
            acc.x += a * v.x; acc.y += a * v.y; acc.z += a * v.z; acc.w += a * v.w;
        }
        acc.x += __shfl_xor_sync(0xffffffffu, acc.x, 16);
        acc.y += __shfl_xor_sync(0xffffffffu, acc.y, 16);
        acc.z += __shfl_xor_sync(0xffffffffu, acc.z, 16);
        acc.w += __shfl_xor_sync(0xffffffffu, acc.w, 16);
        if (half == 0) {
            const float4 sv = ((const float4*)(entity_emb + i_ids[bi] * 64))[c];
            ((float4*)x0_s[elem])[c] = make_float4(sv.x + acc.x, sv.y + acc.y,
                                                   sv.z + acc.z, sv.w + acc.w);
        }
    }
    __syncthreads();

    // ---- P5: layer-0 matvecs; warps 0-3: 8 j each (4 per elem, 16 acc);
    //          warps 4-5: hop-0 elem0; warps 6-7: hop-0 elem1 ----
    if (w < 4) {
        const int j0 = w * 4;
        const float bl = b0[lane], bh = b0[lane + 32];
        float aAl[4], aAh[4], aBl[4], aBh[4];
        #pragma unroll
        for (int q = 0; q < 4; q++) { aAl[q] = bl; aAh[q] = bh; aBl[q] = bl; aBh[q] = bh; }
        #pragma unroll
        for (int dd = 0; dd < 16; dd++) {
            const float4 wl = W0_s[lane * W0PAD + dd];
            const float4 wh = W0_s[(lane + 32) * W0PAD + dd];
            #pragma unroll
            for (int q = 0; q < 4; q++) {
                const float4 xa = ((const float4*)x_s[0][j0 + q])[dd];  // broadcast
                aAl[q] += xa.x*wl.x + xa.y*wl.y + xa.z*wl.z + xa.w*wl.w;
                aAh[q] += xa.x*wh.x + xa.y*wh.y + xa.z*wh.z + xa.w*wh.w;
                const float4 xb = ((const float4*)x_s[1][j0 + q])[dd];  // broadcast
                aBl[q] += xb.x*wl.x + xb.y*wl.y + xb.z*wl.z + xb.w*wl.w;
                aBh[q] += xb.x*wh.x + xb.y*wh.y + xb.z*wh.z + xb.w*wh.w;
            }
        }
        #pragma unroll
        for (int q = 0; q < 4; q++) {
            h1_s[0][j0 + q][lane]      = fmaxf(aAl[q], 0.f);
            h1_s[0][j0 + q][lane + 32] = fmaxf(aAh[q], 0.f);
            h1_s[1][j0 + q][lane]      = fmaxf(aBl[q], 0.f);
            h1_s[1][j0 + q][lane + 32] = fmaxf(aBh[q], 0.f);
        }
    } else {
        const int elem = (w >= 6);
        const int e = (t - 128) & 63;   // 0..63 within each warp pair
        float acc = b0[e];
        const float4* x0v = (const float4*)x0_s[elem];
        #pragma unroll
        for (int dd = 0; dd < 16; dd++) {
            const float4 xv = x0v[dd];
            const float4 wv = W0_s[e * W0PAD + dd];
            acc += xv.x * wv.x + xv.y * wv.y + xv.z * wv.z + xv.w * wv.w;
        }
        h0_s[elem][e] = fmaxf(acc, 0.f);
    }
    __syncthreads();

    // ---- P6: layer-1 hop-0 (reuses attn0), tanh matvec, score x2 ----
    if (t < 128) {
        const int elem = t >> 6, d = t & 63;
        float agg = 0.f;
        #pragma unroll
        for (int k = 0; k < 16; k++) agg += attn0_s[elem][k] * h1_s[elem][k][d];
        x0_s[elem][d] = h0_s[elem][d] + agg;
    }
    __syncthreads();
    if (t < 128) {
        const int elem = t >> 6, d = t & 63;
        float acc = b1[d];
        const float4* w1r = (const float4*)(W1 + d * 64);
        const float4* x0v = (const float4*)x0_s[elem];
        #pragma unroll
        for (int dd = 0; dd < 16; dd++) {
            const float4 xv = x0v[dd];
            const float4 wv = w1r[dd];
            acc += xv.x * wv.x + xv.y * wv.y + xv.z * wv.z + xv.w * wv.w;
        }
        const float item = tanhf(acc);
        float p = ue_s[elem][d] * item;
        #pragma unroll
        for (int o = 16; o; o >>= 1) p += __shfl_xor_sync(0xffffffffu, p, o);
        if (lane == 0) red_s[elem][w & 1] = p;
    }
    __syncthreads();
    if (t < 2) {
        const int bi = 2 * b + t;
        if (bi < B) {
            const float s = red_s[t][0] + red_s[t][1];
            out[bi] = 1.f / (1.f + __expf(-s));
        }
    }
}

extern "C" void kernel_launch(void* const* d_in, const int* in_sizes, int n_in,
                              void* d_out, int out_size) {
    const int*   u_ids        = (const int*)d_in[0];
    const int*   i_ids        = (const int*)d_in[1];
    const int*   adj_entity   = (const int*)d_in[2];
    const int*   adj_relation = (const int*)d_in[3];
    const float* user_emb     = (const float*)d_in[4];
    const float* entity_emb   = (const float*)d_in[5];
    const float* relation_emb = (const float*)d_in[6];
    const float* W0           = (const float*)d_in[7];
    const float* b0           = (const float*)d_in[8];
    const float* W1           = (const float*)d_in[9];
    const float* b1           = (const float*)d_in[10];
    float* out = (float*)d_out;

    const int B = in_sizes[1];
    const int grid = (B + 1) / 2;
    kgnn_kernel<<<grid, 256>>>(u_ids, i_ids, adj_entity, adj_relation,
                               user_emb, entity_emb, relation_emb,
                               W0, b0, W1, b1, out, B);
}

// round 6
// speedup vs baseline: 2.5975x; 1.0373x over previous
#include <cuda_runtime.h>

#define DIM 64
#define KNB 16
#define NREL 33
#define W0PAD 17   // float4 per row -> conflict-free LDS.128

__global__ __launch_bounds__(256, 5) void kgnn_kernel(
    const int* __restrict__ u_ids,
    const int* __restrict__ i_ids,
    const int* __restrict__ adj_entity,
    const int* __restrict__ adj_relation,
    const float* __restrict__ user_emb,
    const float* __restrict__ entity_emb,
    const float* __restrict__ relation_emb,
    const float* __restrict__ W0,
    const float* __restrict__ b0,
    const float* __restrict__ W1,
    const float* __restrict__ b1,
    float* __restrict__ out,
    int B)
{
    __shared__ float4 W0_s[64 * W0PAD];
    __shared__ float  ue_s[2][64];
    __shared__ float  reldot_s[2][NREL];
    __shared__ float  attn_s[2][16][16];
    __shared__ float  attn0_s[2][16];
    __shared__ int    e1_s[2][16], r0_s[2][16];
    __shared__ int    e2_s[2][16][16];
    __shared__ int    r1_s[2][16][16];
    __shared__ __align__(16) float x_s[2][17][64];   // slot 16 = hop-0 vector
    __shared__ __align__(16) float h_s[2][17][64];   // slot 16 = hop-0 hidden
    __shared__ __align__(16) float xf_s[2][64];
    __shared__ float  red_s[2][2];

    const int b    = blockIdx.x;
    const int t    = threadIdx.x;
    const int lane = t & 31;
    const int w    = t >> 5;
    const int bi0  = 2 * b;
    const int bi1  = (2 * b + 1 < B) ? (2 * b + 1) : (B - 1);

    // ---- P1: stage W0, ue x2, hop-0 indices x2 ----
    {
        const float4* W0_4 = (const float4*)W0;
        #pragma unroll
        for (int i = 0; i < 4; i++) {
            int idx = t + i * 256;
            int e = idx >> 4, c = idx & 15;
            W0_s[e * W0PAD + c] = W0_4[idx];
        }
    }
    if (t < 128) {
        const int elem = t >> 6, d = t & 63;
        const int bi = elem ? bi1 : bi0;
        ue_s[elem][d] = user_emb[u_ids[bi] * 64 + d];
    }
    if (t < 32) {
        const int elem = t >> 4, kk = t & 15;
        const int bi = elem ? bi1 : bi0;
        const int e0 = i_ids[bi];
        e1_s[elem][kk] = adj_entity[e0 * KNB + kk];
        r0_s[elem][kk] = adj_relation[e0 * KNB + kk];
    }
    __syncthreads();

    // ---- P2: 66 relation dots + hop-1 index loads ----
    for (int idx = w; idx < 2 * NREL; idx += 8) {
        const int r = idx >> 1, elem = idx & 1;
        float p = ue_s[elem][lane] * relation_emb[r * 64 + lane]
                + ue_s[elem][lane + 32] * relation_emb[r * 64 + 32 + lane];
        #pragma unroll
        for (int o = 16; o; o >>= 1) p += __shfl_xor_sync(0xffffffffu, p, o);
        if (lane == 0) reldot_s[elem][r] = p * (1.f / 64.f);
    }
    {
        const int j = t >> 4, k = t & 15;
        #pragma unroll
        for (int elem = 0; elem < 2; elem++) {
            const int ej = e1_s[elem][j];
            e2_s[elem][j][k] = adj_entity[ej * KNB + k];
            r1_s[elem][j][k] = adj_relation[ej * KNB + k];
        }
    }
    __syncthreads();

    // ---- P3: attention lookup + 16-lane softmax ----
    {
        const int j = t >> 4, k = t & 15;
        #pragma unroll
        for (int elem = 0; elem < 2; elem++) {
            float s = reldot_s[elem][r1_s[elem][j][k]];
            float m = s;
            #pragma unroll
            for (int o = 8; o; o >>= 1) m = fmaxf(m, __shfl_xor_sync(0xffffffffu, m, o));
            float ex = __expf(s - m);
            float sum = ex;
            #pragma unroll
            for (int o = 8; o; o >>= 1) sum += __shfl_xor_sync(0xffffffffu, sum, o);
            attn_s[elem][j][k] = ex / sum * (1.f / 16.f);
        }
    }
    if (t < 32) {
        const int elem = t >> 4, k = t & 15;
        float s = reldot_s[elem][r0_s[elem][k]];
        float m = s;
        #pragma unroll
        for (int o = 8; o; o >>= 1) m = fmaxf(m, __shfl_xor_sync(0xffffffffu, m, o));
        float ex = __expf(s - m);
        float sum = ex;
        #pragma unroll
        for (int o = 8; o; o >>= 1) sum += __shfl_xor_sync(0xffffffffu, sum, o);
        attn0_s[elem][k] = ex / sum * (1.f / 16.f);
    }
    __syncthreads();

    // ---- P4: float4 entity gathers: 32 j rows + 2 hop-0 rows ----
    const int half = lane >> 4;
    const int c    = lane & 15;
    #pragma unroll
    for (int jj = 0; jj < 4; jj++) {
        const int jg   = w + jj * 8;          // 0..31
        const int elem = jg >> 4, j = jg & 15;
        float4 acc = make_float4(0.f, 0.f, 0.f, 0.f);
        #pragma unroll
        for (int kk = 0; kk < 8; kk++) {
            const int k = kk * 2 + half;
            const float4 v = ((const float4*)(entity_emb + e2_s[elem][j][k] * 64))[c];
            const float a = attn_s[elem][j][k];
            acc.x += a * v.x; acc.y += a * v.y; acc.z += a * v.z; acc.w += a * v.w;
        }
        acc.x += __shfl_xor_sync(0xffffffffu, acc.x, 16);
        acc.y += __shfl_xor_sync(0xffffffffu, acc.y, 16);
        acc.z += __shfl_xor_sync(0xffffffffu, acc.z, 16);
        acc.w += __shfl_xor_sync(0xffffffffu, acc.w, 16);
        if (half == 0) {
            const float4 sv = ((const float4*)(entity_emb + e1_s[elem][j] * 64))[c];
            ((float4*)x_s[elem][j])[c] = make_float4(sv.x + acc.x, sv.y + acc.y,
                                                     sv.z + acc.z, sv.w + acc.w);
        }
    }
    if (w < 2) {  // hop-0 aggregate -> slot 16
        const int elem = w;
        const int bi = elem ? bi1 : bi0;
        float4 acc = make_float4(0.f, 0.f, 0.f, 0.f);
        #pragma unroll
        for (int kk = 0; kk < 8; kk++) {
            const int k = kk * 2 + half;
            const float4 v = ((const float4*)(entity_emb + e1_s[elem][k] * 64))[c];
            const float a = attn0_s[elem][k];
            acc.x += a * v.x; acc.y += a * v.y; acc.z += a * v.z; acc.w += a * v.w;
        }
        acc.x += __shfl_xor_sync(0xffffffffu, acc.x, 16);
        acc.y += __shfl_xor_sync(0xffffffffu, acc.y, 16);
        acc.z += __shfl_xor_sync(0xffffffffu, acc.z, 16);
        acc.w += __shfl_xor_sync(0xffffffffu, acc.w, 16);
        if (half == 0) {
            const float4 sv = ((const float4*)(entity_emb + i_ids[bi] * 64))[c];
            ((float4*)x_s[elem][16])[c] = make_float4(sv.x + acc.x, sv.y + acc.y,
                                                      sv.z + acc.z, sv.w + acc.w);
        }
    }
    __syncthreads();

    // ---- P5: 34 layer-0 matvecs flattened; warp w -> flat 4w..4w+3,
    //          warps 0,1 also take flat 32,33. 8-10 acc/thread. ----
    {
        const float* xflat = &x_s[0][0][0];
        float*       hflat = &h_s[0][0][0];
        const float bl = b0[lane], bh = b0[lane + 32];
        float al[5], ah[5];
        #pragma unroll
        for (int q = 0; q < 5; q++) { al[q] = bl; ah[q] = bh; }
        const int f4 = w * 4;
        const int f5 = 32 + w;                // valid only for w<2
        const bool has5 = (w < 2);
        #pragma unroll
        for (int dd = 0; dd < 16; dd++) {
            const float4 wl = W0_s[lane * W0PAD + dd];
            const float4 wh = W0_s[(lane + 32) * W0PAD + dd];
            #pragma unroll
            for (int q = 0; q < 4; q++) {
                const float4 xv = ((const float4*)(xflat + (f4 + q) * 64))[dd];
                al[q] += xv.x*wl.x + xv.y*wl.y + xv.z*wl.z + xv.w*wl.w;
                ah[q] += xv.x*wh.x + xv.y*wh.y + xv.z*wh.z + xv.w*wh.w;
            }
            if (has5) {
                const float4 xv = ((const float4*)(xflat + f5 * 64))[dd];
                al[4] += xv.x*wl.x + xv.y*wl.y + xv.z*wl.z + xv.w*wl.w;
                ah[4] += xv.x*wh.x + xv.y*wh.y + xv.z*wh.z + xv.w*wh.w;
            }
        }
        #pragma unroll
        for (int q = 0; q < 4; q++) {
            hflat[(f4 + q) * 64 + lane]      = fmaxf(al[q], 0.f);
            hflat[(f4 + q) * 64 + lane + 32] = fmaxf(ah[q], 0.f);
        }
        if (has5) {
            hflat[f5 * 64 + lane]      = fmaxf(al[4], 0.f);
            hflat[f5 * 64 + lane + 32] = fmaxf(ah[4], 0.f);
        }
    }
    __syncthreads();

    // ---- P6: layer-1 hop-0 combine (reuses attn0), tanh matvec, score ----
    if (t < 128) {
        const int elem = t >> 6, d = t & 63;
        float agg = 0.f;
        #pragma unroll
        for (int k = 0; k < 16; k++) agg += attn0_s[elem][k] * h_s[elem][k][d];
        xf_s[elem][d] = h_s[elem][16][d] + agg;
    }
    __syncthreads();
    if (t < 128) {
        const int elem = t >> 6, d = t & 63;
        float acc = b1[d];
        const float4* w1r = (const float4*)(W1 + d * 64);
        const float4* x0v = (const float4*)xf_s[elem];
        #pragma unroll
        for (int dd = 0; dd < 16; dd++) {
            const float4 xv = x0v[dd];
            const float4 wv = w1r[dd];
            acc += xv.x * wv.x + xv.y * wv.y + xv.z * wv.z + xv.w * wv.w;
        }
        const float item = tanhf(acc);
        float p = ue_s[elem][d] * item;
        #pragma unroll
        for (int o = 16; o; o >>= 1) p += __shfl_xor_sync(0xffffffffu, p, o);
        if (lane == 0) red_s[elem][w & 1] = p;
    }
    __syncthreads();
    if (t < 2) {
        const int bi = 2 * b + t;
        if (bi < B) {
            const float s = red_s[t][0] + red_s[t][1];
            out[bi] = 1.f / (1.f + __expf(-s));
        }
    }
}

extern "C" void kernel_launch(void* const* d_in, const int* in_sizes, int n_in,
                              void* d_out, int out_size) {
    const int*   u_ids        = (const int*)d_in[0];
    const int*   i_ids        = (const int*)d_in[1];
    const int*   adj_entity   = (const int*)d_in[2];
    const int*   adj_relation = (const int*)d_in[3];
    const float* user_emb     = (const float*)d_in[4];
    const float* entity_emb   = (const float*)d_in[5];
    const float* relation_emb = (const float*)d_in[6];
    const float* W0           = (const float*)d_in[7];
    const float* b0           = (const float*)d_in[8];
    const float* W1           = (const float*)d_in[9];
    const float* b1           = (const float*)d_in[10];
    float* out = (float*)d_out;

    const int B = in_sizes[1];
    const int grid = (B + 1) / 2;
    kgnn_kernel<<<grid, 256>>>(u_ids, i_ids, adj_entity, adj_relation,
                               user_emb, entity_emb, relation_emb,
                               W0, b0, W1, b1, out, B);
}